// round 1
// baseline (speedup 1.0000x reference)
#include <cuda_runtime.h>
#include <cstddef>

#define Bsz 256
#define Lsz 2048
#define BL  (Bsz*Lsz)   // 524288 tokens

// ---------------- scratch (device globals: no allocation allowed) ----------------
// Gate pre/post-activations, channel-major: row o in [0,256): [zf|htf|zb|htb] x 64ch, each row BL floats
__device__ float g_G[256u * BL];          // 537 MB
__device__ float g_Hf[(size_t)BL * 64];   // forward prestates, token-major [BL][64]
__device__ float g_Hb[(size_t)BL * 64];   // backward prestates
__device__ float g_T[4 * 64 * 64];        // prep temp: A_g @ P_t
__device__ float g_gateW[68 * 256];       // folded gate weights, k-major [68][256]
__device__ float g_gateB[256];
__device__ float g_headW[192 * 128];      // folded head weights, k-major [192][128]
__device__ float g_headB[128];

// ---------------- prep: fold weights ----------------
// gate pre-act for row-block g (0:zf 1:htf 2:zb 3:htb):
//   A·(P3 x3 + Pt t_enc + pb) + ab  =  (A P3) x3 + (A Pt te_w2) r + [A Pt te_b2 + A pb + ab]
__global__ void prepA_kernel(const float* fwz, const float* fbz, const float* fwh, const float* fbh,
                             const float* bwz, const float* bbz, const float* bwh, const float* bbh,
                             const float* fpw, const float* fpb, const float* bpw, const float* bpb)
{
    int tid = threadIdx.x;              // 256 threads
    int g = tid >> 6, i = tid & 63;
    const float* A  = (g==0) ? fwz : (g==1) ? fwh : (g==2) ? bwz : bwh;
    const float* ab = (g==0) ? fbz : (g==1) ? fbh : (g==2) ? bbz : bbh;
    const float* P  = (g<2) ? fpw : bpw;
    const float* pb = (g<2) ? fpb : bpb;

    for (int j = 0; j < 64; ++j) {
        float s = 0.f;
        for (int h = 0; h < 64; ++h) s = fmaf(A[i*64+h], P[h*67 + 3 + j], s);
        g_T[(size_t)(g*64+i)*64 + j] = s;
    }
    for (int c = 0; c < 3; ++c) {
        float s = 0.f;
        for (int h = 0; h < 64; ++h) s = fmaf(A[i*64+h], P[h*67 + c], s);
        g_gateW[c*256 + g*64 + i] = s;
    }
    float s = ab[i];
    for (int h = 0; h < 64; ++h) s = fmaf(A[i*64+h], pb[h], s);
    g_gateB[g*64 + i] = s;              // partial; prepB adds T·te_b2
    g_gateW[67*256 + tid] = 0.f;        // pad column
}

__global__ void prepB_kernel(const float* tew2, const float* teb2)
{
    int o = threadIdx.x;                // 256 threads
    const float* T = &g_T[(size_t)o * 64];
    for (int k = 0; k < 64; ++k) {
        float s = 0.f;
        for (int j = 0; j < 64; ++j) s = fmaf(T[j], tew2[j*64 + k], s);
        g_gateW[(3+k)*256 + o] = s;
    }
    float s = 0.f;
    for (int j = 0; j < 64; ++j) s = fmaf(T[j], teb2[j], s);
    g_gateB[o] += s;
}

// head: hid = relu(U1 h_f + U2 h_b + (U3 te_w2) r + [gh_b1 + U3 te_b2])
__global__ void prepHead_kernel(const float* ghw1, const float* ghb1,
                                const float* tew2, const float* teb2)
{
    int o = threadIdx.x;                // 128 threads
    for (int k = 0; k < 128; ++k) g_headW[k*128 + o] = ghw1[o*192 + k];
    for (int k = 0; k < 64; ++k) {
        float s = 0.f;
        for (int j = 0; j < 64; ++j) s = fmaf(ghw1[o*192 + 128 + j], tew2[j*64 + k], s);
        g_headW[(128+k)*128 + o] = s;
    }
    float s = ghb1[o];
    for (int j = 0; j < 64; ++j) s = fmaf(ghw1[o*192 + 128 + j], teb2[j], s);
    g_headB[o] = s;
}

// ---------------- gates GEMM: per token, 256 outputs = W[256x68] * act[68] ----------------
// block: 512 threads, 128 tokens, 256 outputs, K=68; thread computes 8 outs x 8 toks
#define GATES_SMEM ((68*256 + 68*128) * 4)

__global__ void __launch_bounds__(512, 1)
gates_kernel(const float* __restrict__ x, const float* __restrict__ tt,
             const float* __restrict__ mtok,
             const float* __restrict__ tew1, const float* __restrict__ teb1)
{
    extern __shared__ float sm[];
    float* Wsm = sm;                 // [68][256]
    float* Asm = sm + 68*256;        // [68][128]
    __shared__ float tv[128];
    const int tid = threadIdx.x;
    const size_t base = (size_t)blockIdx.x * 128;

    for (int i = tid; i < 68*256/4; i += 512)
        ((float4*)Wsm)[i] = ((const float4*)g_gateW)[i];

    if (tid < 128) {
        size_t g = base + tid;
        float m  = x[g*3 + 2];
        float x0 = x[g*3 + 0];
        float x1 = x[g*3 + 1];
        if (m == 0.f) { x0 = mtok[0]; x1 = mtok[1]; }
        Asm[0*128 + tid] = x0;
        Asm[1*128 + tid] = x1;
        Asm[2*128 + tid] = m;
        Asm[67*128 + tid] = 0.f;
        tv[tid] = tt[g];
    }
    __syncthreads();
    for (int idx = tid; idx < 64*128; idx += 512) {
        int k = idx >> 7, tok = idx & 127;
        Asm[(3+k)*128 + tok] = fmaxf(fmaf(tew1[k], tv[tok], teb1[k]), 0.f);
    }
    __syncthreads();

    const int o0 = (tid >> 4) * 8;
    const int t0 = (tid & 15) * 8;
    float acc[8][8];
#pragma unroll
    for (int i = 0; i < 8; ++i)
#pragma unroll
        for (int j = 0; j < 8; ++j) acc[i][j] = 0.f;

#pragma unroll 4
    for (int k = 0; k < 68; ++k) {
        float4 a0 = *(const float4*)&Asm[k*128 + t0];
        float4 a1 = *(const float4*)&Asm[k*128 + t0 + 4];
        float4 w0 = *(const float4*)&Wsm[k*256 + o0];
        float4 w1 = *(const float4*)&Wsm[k*256 + o0 + 4];
        float a[8] = {a0.x,a0.y,a0.z,a0.w,a1.x,a1.y,a1.z,a1.w};
        float w[8] = {w0.x,w0.y,w0.z,w0.w,w1.x,w1.y,w1.z,w1.w};
#pragma unroll
        for (int oi = 0; oi < 8; ++oi)
#pragma unroll
            for (int tj = 0; tj < 8; ++tj)
                acc[oi][tj] = fmaf(w[oi], a[tj], acc[oi][tj]);
    }

#pragma unroll
    for (int oi = 0; oi < 8; ++oi) {
        int o = o0 + oi;
        float bb = g_gateB[o];
        bool sig = ((o >> 6) & 1) == 0;   // rows 0-63, 128-191: sigmoid; else tanh
        float outv[8];
#pragma unroll
        for (int tj = 0; tj < 8; ++tj) {
            float v = acc[oi][tj] + bb;
            if (sig) {
                v = __fdividef(1.f, 1.f + __expf(-v));
            } else {
                float e  = __expf(-2.f * fabsf(v));
                float th = __fdividef(1.f - e, 1.f + e);
                v = copysignf(th, v);
            }
            outv[tj] = v;
        }
        float* dst = &g_G[(size_t)o * BL + base + t0];
        *(float4*)(dst)     = make_float4(outv[0], outv[1], outv[2], outv[3]);
        *(float4*)(dst + 4) = make_float4(outv[4], outv[5], outv[6], outv[7]);
    }
}

// ---------------- scan: 2 dirs x 256 batches x 64 channels, serial over L ----------------
__global__ void __launch_bounds__(64, 8)
scan_kernel()
{
    const int b   = blockIdx.x;
    const int dir = blockIdx.y;
    const int ch  = threadIdx.x;
    const float* zp = g_G + (size_t)(dir*128 + ch)      * BL + (size_t)b * Lsz;
    const float* hp = g_G + (size_t)(dir*128 + 64 + ch) * BL + (size_t)b * Lsz;
    float* op = (dir ? g_Hb : g_Hf) + (size_t)b * Lsz * 64 + ch;
    float h = 0.f;
    if (dir == 0) {
        for (int t = 0; t < Lsz; t += 4) {
            float4 z = *(const float4*)(zp + t);
            float4 q = *(const float4*)(hp + t);
            op[(size_t)(t+0)*64] = h; h = fmaf(z.x, q.x - h, h);
            op[(size_t)(t+1)*64] = h; h = fmaf(z.y, q.y - h, h);
            op[(size_t)(t+2)*64] = h; h = fmaf(z.z, q.z - h, h);
            op[(size_t)(t+3)*64] = h; h = fmaf(z.w, q.w - h, h);
        }
    } else {
        for (int t = Lsz - 4; t >= 0; t -= 4) {
            float4 z = *(const float4*)(zp + t);
            float4 q = *(const float4*)(hp + t);
            op[(size_t)(t+3)*64] = h; h = fmaf(z.w, q.w - h, h);
            op[(size_t)(t+2)*64] = h; h = fmaf(z.z, q.z - h, h);
            op[(size_t)(t+1)*64] = h; h = fmaf(z.y, q.y - h, h);
            op[(size_t)(t+0)*64] = h; h = fmaf(z.x, q.x - h, h);
        }
    }
}

// ---------------- head GEMM: 128 outs x K=192 ([h_f|h_b|r]) + 128->1 reduction ----------------
#define HEAD_SMEM ((192*128 + 192*128 + 16*128) * 4)

__global__ void __launch_bounds__(256, 1)
head_kernel(const float* __restrict__ x, const float* __restrict__ tt,
            const float* __restrict__ tew1, const float* __restrict__ teb1,
            const float* __restrict__ ghw2, const float* __restrict__ ghb2,
            float* __restrict__ out)
{
    extern __shared__ float sm[];
    float* Wsm = sm;                      // [192][128]
    float* Asm = Wsm + 192*128;           // [192][128]
    float* red = Asm + 192*128;           // [16][128]
    __shared__ __align__(16) float hff[64];
    __shared__ __align__(16) float hbf[64];
    __shared__ float tv[128];
    const int tid = threadIdx.x;
    const size_t base = (size_t)blockIdx.x * 128;
    const int b = (int)(base / Lsz);      // 2048 % 128 == 0: one batch per block

    for (int i = tid; i < 192*128/4; i += 256)
        ((float4*)Wsm)[i] = ((const float4*)g_headW)[i];

    if (tid < 64)        hff[tid]      = g_Hf[((size_t)b*Lsz + (Lsz-1))*64 + tid];
    else if (tid < 128)  hbf[tid - 64] = g_Hb[(size_t)b*Lsz*64 + (tid - 64)];
    if (tid < 128) tv[tid] = tt[base + tid];
    __syncthreads();

    {   // rows 0-63: h_fwd (w/ masked->final), 64-127: h_bwd
        const int tok  = tid & 127;
        const int half = tid >> 7;
        const size_t g = base + tok;
        const float m  = x[g*3 + 2];
        const bool um  = m > 0.f;
        const float* src = (half ? g_Hb : g_Hf) + g * 64;
        const float* fin = half ? hbf : hff;
#pragma unroll
        for (int k = 0; k < 64; k += 4) {
            float4 v = *(const float4*)(src + k);
            float4 f = *(const float4*)(fin + k);
            float4 w = um ? v : f;
            int row = half*64 + k;
            Asm[(row+0)*128 + tok] = w.x;
            Asm[(row+1)*128 + tok] = w.y;
            Asm[(row+2)*128 + tok] = w.z;
            Asm[(row+3)*128 + tok] = w.w;
        }
    }
    for (int idx = tid; idx < 64*128; idx += 256) {   // rows 128-191: r
        int k = idx >> 7, tok = idx & 127;
        Asm[(128+k)*128 + tok] = fmaxf(fmaf(tew1[k], tv[tok], teb1[k]), 0.f);
    }
    __syncthreads();

    const int o0 = (tid >> 4) * 8;
    const int t0 = (tid & 15) * 8;
    float acc[8][8];
#pragma unroll
    for (int i = 0; i < 8; ++i)
#pragma unroll
        for (int j = 0; j < 8; ++j) acc[i][j] = 0.f;

#pragma unroll 4
    for (int k = 0; k < 192; ++k) {
        float4 a0 = *(const float4*)&Asm[k*128 + t0];
        float4 a1 = *(const float4*)&Asm[k*128 + t0 + 4];
        float4 w0 = *(const float4*)&Wsm[k*128 + o0];
        float4 w1 = *(const float4*)&Wsm[k*128 + o0 + 4];
        float a[8] = {a0.x,a0.y,a0.z,a0.w,a1.x,a1.y,a1.z,a1.w};
        float w[8] = {w0.x,w0.y,w0.z,w0.w,w1.x,w1.y,w1.z,w1.w};
#pragma unroll
        for (int oi = 0; oi < 8; ++oi)
#pragma unroll
            for (int tj = 0; tj < 8; ++tj)
                acc[oi][tj] = fmaf(w[oi], a[tj], acc[oi][tj]);
    }

    float part[8];
#pragma unroll
    for (int tj = 0; tj < 8; ++tj) part[tj] = 0.f;
#pragma unroll
    for (int oi = 0; oi < 8; ++oi) {
        int o = o0 + oi;
        float bb = g_headB[o];
        float w2 = ghw2[o];
#pragma unroll
        for (int tj = 0; tj < 8; ++tj)
            part[tj] = fmaf(w2, fmaxf(acc[oi][tj] + bb, 0.f), part[tj]);
    }
#pragma unroll
    for (int tj = 0; tj < 8; ++tj)
        red[(tid >> 4)*128 + t0 + tj] = part[tj];
    __syncthreads();
    if (tid < 128) {
        float s = ghb2[0];
#pragma unroll
        for (int g2 = 0; g2 < 16; ++g2) s += red[g2*128 + tid];
        out[base + tid] = s;
    }
}

// ---------------- launch ----------------
extern "C" void kernel_launch(void* const* d_in, const int* in_sizes, int n_in,
                              void* d_out, int out_size)
{
    (void)in_sizes; (void)n_in; (void)out_size;
    const float* x    = (const float*)d_in[0];
    const float* t    = (const float*)d_in[1];
    const float* mtok = (const float*)d_in[2];
    const float* tew1 = (const float*)d_in[3];
    const float* teb1 = (const float*)d_in[4];
    const float* tew2 = (const float*)d_in[5];
    const float* teb2 = (const float*)d_in[6];
    const float* fpw  = (const float*)d_in[7];
    const float* fpb  = (const float*)d_in[8];
    const float* bpw  = (const float*)d_in[9];
    const float* bpb  = (const float*)d_in[10];
    const float* fwz  = (const float*)d_in[11];
    const float* fbz  = (const float*)d_in[12];
    const float* fwh  = (const float*)d_in[13];
    const float* fbh  = (const float*)d_in[14];
    const float* bwz  = (const float*)d_in[15];
    const float* bbz  = (const float*)d_in[16];
    const float* bwh  = (const float*)d_in[17];
    const float* bbh  = (const float*)d_in[18];
    const float* ghw1 = (const float*)d_in[19];
    const float* ghb1 = (const float*)d_in[20];
    const float* ghw2 = (const float*)d_in[21];
    const float* ghb2 = (const float*)d_in[22];
    float* out = (float*)d_out;

    cudaFuncSetAttribute(gates_kernel, cudaFuncAttributeMaxDynamicSharedMemorySize, GATES_SMEM);
    cudaFuncSetAttribute(head_kernel,  cudaFuncAttributeMaxDynamicSharedMemorySize, HEAD_SMEM);

    prepA_kernel<<<1, 256>>>(fwz, fbz, fwh, fbh, bwz, bbz, bwh, bbh, fpw, fpb, bpw, bpb);
    prepB_kernel<<<1, 256>>>(tew2, teb2);
    prepHead_kernel<<<1, 128>>>(ghw1, ghb1, tew2, teb2);

    gates_kernel<<<BL/128, 512, GATES_SMEM>>>(x, t, mtok, tew1, teb1);
    scan_kernel<<<dim3(Bsz, 2), 64>>>();
    head_kernel<<<BL/128, 256, HEAD_SMEM>>>(x, t, tew1, teb1, ghw2, ghb2, out);
}